// round 3
// baseline (speedup 1.0000x reference)
#include <cuda_runtime.h>

#define C        384
#define NQKV     1152
#define NWIN     2048   // 32 images * 64 windows
#define D        64     // tokens per window

// Scratch (device globals are the sanctioned scratch mechanism).
__device__ float g_qkv[(size_t)NWIN * D * NQKV];  // [m][3*384] qkv
__device__ float g_ctx[(size_t)NWIN * D * C];     // [m][384] attention output

namespace {
struct ForceLoad {
    ForceLoad() {
        void* p = nullptr;
        cudaGetSymbolAddress(&p, g_qkv);
        cudaGetSymbolAddress(&p, g_ctx);
    }
};
ForceLoad g_force_load;
}

// ---------------------------------------------------------------------------
// Packed fp32x2 helpers (Blackwell dual-fp32 pipe).
// ---------------------------------------------------------------------------
typedef unsigned long long u64;

__device__ __forceinline__ u64 pack2(float a, float b) {
    u64 r;
    asm("mov.b64 %0, {%1, %2};" : "=l"(r) : "f"(a), "f"(b));
    return r;
}
__device__ __forceinline__ void ffma2(u64& d, u64 a, u64 b) {
    asm("fma.rn.f32x2 %0, %1, %2, %0;" : "+l"(d) : "l"(a), "l"(b));
}
__device__ __forceinline__ float2 unpack2(u64 v) {
    float x, y;
    asm("mov.b64 {%0, %1}, %2;" : "=f"(x), "=f"(y) : "l"(v));
    return make_float2(x, y);
}

// ---------------------------------------------------------------------------
// GEMM body: Acc[128,128] += A[128,384] * W[384,ldw](cols n0..n0+127)
// 256 threads as 16x16 grid; thread tile 8(m) x 8(n) packed f32x2.
// A rows provided via 4 per-thread staging pointers (k0-invariant).
// As2 holds A values pre-duplicated as (a,a) float2 pairs.
// ---------------------------------------------------------------------------
__device__ __forceinline__ void gemm_body(
    const float* ap0, const float* ap1, const float* ap2, const float* ap3,
    int arow0, int arow1, int arow2, int arow3,
    const float* __restrict__ w, int ldw, int n0, int tid,
    u64 acc2[8][4], float2 (*As2)[32], float (*Bs)[128])
{
    const int tn8 = (tid & 15) << 3;
    const int tm8 = (tid >> 4) << 3;
    const int bkk = tid >> 5;          // 0..7 (+8 per iter)
    const int bcq = (tid & 31) << 2;
    const float* wp = w + (size_t)bkk * ldw + n0 + bcq;

    for (int k0 = 0; k0 < C; k0 += 32) {
        __syncthreads();
        // Stage A: 4 float4 per thread -> duplicated float2 pairs
        {
            const int kq = (tid & 7) << 2;
            float4 v0 = *(const float4*)(ap0 + k0 + kq);
            float4 v1 = *(const float4*)(ap1 + k0 + kq);
            float4 v2 = *(const float4*)(ap2 + k0 + kq);
            float4 v3 = *(const float4*)(ap3 + k0 + kq);
            As2[arow0][kq]     = make_float2(v0.x, v0.x);
            As2[arow0][kq + 1] = make_float2(v0.y, v0.y);
            As2[arow0][kq + 2] = make_float2(v0.z, v0.z);
            As2[arow0][kq + 3] = make_float2(v0.w, v0.w);
            As2[arow1][kq]     = make_float2(v1.x, v1.x);
            As2[arow1][kq + 1] = make_float2(v1.y, v1.y);
            As2[arow1][kq + 2] = make_float2(v1.z, v1.z);
            As2[arow1][kq + 3] = make_float2(v1.w, v1.w);
            As2[arow2][kq]     = make_float2(v2.x, v2.x);
            As2[arow2][kq + 1] = make_float2(v2.y, v2.y);
            As2[arow2][kq + 2] = make_float2(v2.z, v2.z);
            As2[arow2][kq + 3] = make_float2(v2.w, v2.w);
            As2[arow3][kq]     = make_float2(v3.x, v3.x);
            As2[arow3][kq + 1] = make_float2(v3.y, v3.y);
            As2[arow3][kq + 2] = make_float2(v3.z, v3.z);
            As2[arow3][kq + 3] = make_float2(v3.w, v3.w);
        }
        // Stage B: [32 x 128], 4 float4 per thread
#pragma unroll
        for (int s = 0; s < 4; ++s)
            *(float4*)&Bs[bkk + 8 * s][bcq] =
                *(const float4*)(wp + (size_t)(k0 + 8 * s) * ldw);
        __syncthreads();

#pragma unroll
        for (int k = 0; k < 32; k += 2) {
            longlong2 b0a = *(const longlong2*)&Bs[k][tn8];
            longlong2 b0b = *(const longlong2*)&Bs[k][tn8 + 4];
            longlong2 b1a = *(const longlong2*)&Bs[k + 1][tn8];
            longlong2 b1b = *(const longlong2*)&Bs[k + 1][tn8 + 4];
#pragma unroll
            for (int i = 0; i < 8; ++i) {
                longlong2 aa = *(const longlong2*)&As2[tm8 + i][k];
                ffma2(acc2[i][0], (u64)aa.x, (u64)b0a.x);
                ffma2(acc2[i][1], (u64)aa.x, (u64)b0a.y);
                ffma2(acc2[i][2], (u64)aa.x, (u64)b0b.x);
                ffma2(acc2[i][3], (u64)aa.x, (u64)b0b.y);
                ffma2(acc2[i][0], (u64)aa.y, (u64)b1a.x);
                ffma2(acc2[i][1], (u64)aa.y, (u64)b1a.y);
                ffma2(acc2[i][2], (u64)aa.y, (u64)b1b.x);
                ffma2(acc2[i][3], (u64)aa.y, (u64)b1b.y);
            }
        }
    }
}

// Map a 0..127 row of a 2-window CTA (block wpair) to the gathered x pointer.
__device__ __forceinline__ const float* qkv_row_ptr(const float* x, int wpair, int row) {
    int win = wpair * 2 + (row >> 6);
    int img = win >> 6, wi = win & 63, wr = wi >> 3, wc = wi & 7;
    int t = row & 63, ri = t >> 3, ci = t & 7;
    int gr = (wr * 8 + ri + 4) & 63;
    int gc = (wc * 8 + ci + 4) & 63;
    return x + (((size_t)img * 64 + gr) * 64 + gc) * C;
}

// ---------------------------------------------------------------------------
// Kernel 1: QKV projection. grid = (9, 1024). 2 windows (128 rows) per CTA.
// ---------------------------------------------------------------------------
__global__ __launch_bounds__(256, 2) void qkv_kernel(
    const float* __restrict__ x, const float* __restrict__ w,
    const float* __restrict__ bias)
{
    __shared__ float2 As2[128][32];
    __shared__ float  Bs[32][128];
    const int tid = threadIdx.x;
    const int wpair = blockIdx.y;
    const int n0  = blockIdx.x * 128;

    const int arow0 = tid >> 3;
    const int arow1 = arow0 + 32, arow2 = arow0 + 64, arow3 = arow0 + 96;
    const float* ap0 = qkv_row_ptr(x, wpair, arow0);
    const float* ap1 = qkv_row_ptr(x, wpair, arow1);
    const float* ap2 = qkv_row_ptr(x, wpair, arow2);
    const float* ap3 = qkv_row_ptr(x, wpair, arow3);

    u64 acc2[8][4];
#pragma unroll
    for (int i = 0; i < 8; ++i)
#pragma unroll
        for (int j = 0; j < 4; ++j) acc2[i][j] = 0ull;

    gemm_body(ap0, ap1, ap2, ap3, arow0, arow1, arow2, arow3,
              w, NQKV, n0, tid, acc2, As2, Bs);

    const int tn8 = (tid & 15) << 3;
    const int tm8 = (tid >> 4) << 3;
    const float4 bb0 = *(const float4*)&bias[n0 + tn8];
    const float4 bb1 = *(const float4*)&bias[n0 + tn8 + 4];
#pragma unroll
    for (int i = 0; i < 8; ++i) {
        size_t m = (size_t)wpair * 128 + tm8 + i;
        float2 a0 = unpack2(acc2[i][0]);
        float2 a1 = unpack2(acc2[i][1]);
        float2 a2 = unpack2(acc2[i][2]);
        float2 a3 = unpack2(acc2[i][3]);
        float* op = &g_qkv[m * NQKV + n0 + tn8];
        *(float4*)op       = make_float4(a0.x + bb0.x, a0.y + bb0.y,
                                         a1.x + bb0.z, a1.y + bb0.w);
        *(float4*)(op + 4) = make_float4(a2.x + bb1.x, a2.y + bb1.y,
                                         a3.x + bb1.z, a3.y + bb1.w);
    }
}

// ---------------------------------------------------------------------------
// Kernel 2: attention per (window, head). grid = (2048, 12), 256 threads.
// ---------------------------------------------------------------------------
__global__ __launch_bounds__(256) void attn_kernel(const float* __restrict__ bt)
{
    __shared__ float qs[64][32];
    __shared__ float ks[64][36];
    __shared__ float vs[64][36];
    __shared__ float ps[64][68];
    __shared__ int   s_sum[64];
    __shared__ int   s_regn[64];
    __shared__ float s_bias[32];

    const int tid = threadIdx.x;
    const int win = blockIdx.x;
    const int h   = blockIdx.y;
    const float scale = 0.17677669529663687f;  // 1/sqrt(32)

    if (tid < 64) {
        int wi = win & 63, wr = wi >> 3, wc = wi & 7;
        int ri = tid >> 3, ci = tid & 7;
        s_sum[tid] = ri + ci;
        int gr = wr * 8 + ri, gc = wc * 8 + ci;
        int rb = gr < 56 ? 0 : (gr < 60 ? 1 : 2);
        int cb = gc < 56 ? 0 : (gc < 60 ? 1 : 2);
        s_regn[tid] = rb * 3 + cb;
    }
    if (tid >= 64 && tid < 93) {
        int u = tid - 64;                    // bias idx range is [15, 43]
        s_bias[u] = bt[(u + 15) * 12 + h];
    }

    const size_t base = ((size_t)win * D) * NQKV + (size_t)h * 32;
#pragma unroll
    for (int s = 0; s < 2; ++s) {
        int slot = tid + 256 * s;
        int row  = slot >> 3;
        int eq   = (slot & 7) << 2;
        const float* src = &g_qkv[base + (size_t)row * NQKV + eq];
        float4 q4 = *(const float4*)(src);
        q4.x *= scale; q4.y *= scale; q4.z *= scale; q4.w *= scale;
        *(float4*)&qs[row][eq] = q4;
        *(float4*)&ks[row][eq] = *(const float4*)(src + 384);
        *(float4*)&vs[row][eq] = *(const float4*)(src + 768);
    }
    __syncthreads();

    const int i  = tid >> 2;   // query row, 4 threads per row
    const int jg = tid & 3;
    u64 q2[16];
#pragma unroll
    for (int e = 0; e < 32; e += 4) {
        float4 qq = *(const float4*)&qs[i][e];
        q2[(e >> 1)]     = pack2(qq.x, qq.y);
        q2[(e >> 1) + 1] = pack2(qq.z, qq.w);
    }
    const int isum  = s_sum[i];
    const int iregn = s_regn[i];

    float sc[16];
    float mx = -1e30f;
#pragma unroll
    for (int jj = 0; jj < 16; ++jj) {
        int j = (jj << 2) + jg;
        u64 acc2 = 0ull;
#pragma unroll
        for (int e = 0; e < 32; e += 4) {
            float4 k4 = *(const float4*)&ks[j][e];
            ffma2(acc2, q2[(e >> 1)],     pack2(k4.x, k4.y));
            ffma2(acc2, q2[(e >> 1) + 1], pack2(k4.z, k4.w));
        }
        float2 ap = unpack2(acc2);
        float acc = ap.x + ap.y;
        acc += s_bias[isum - s_sum[j] + 14];
        if (iregn != s_regn[j]) acc -= 100.f;
        sc[jj] = acc;
        mx = fmaxf(mx, acc);
    }
    mx = fmaxf(mx, __shfl_xor_sync(0xffffffffu, mx, 1));
    mx = fmaxf(mx, __shfl_xor_sync(0xffffffffu, mx, 2));

    float sum = 0.f;
#pragma unroll
    for (int jj = 0; jj < 16; ++jj) {
        float e = __expf(sc[jj] - mx);
        sc[jj] = e;
        sum += e;
    }
    sum += __shfl_xor_sync(0xffffffffu, sum, 1);
    sum += __shfl_xor_sync(0xffffffffu, sum, 2);
    float inv = 1.f / sum;
#pragma unroll
    for (int jj = 0; jj < 16; ++jj) ps[i][(jj << 2) + jg] = sc[jj] * inv;
    __syncthreads();

    // out[i][e0..e0+7] = sum_j P[i][j] * v[j][e], packed f32x2
    const int e0 = (tid & 3) << 3;
    u64 o2[4] = {0ull, 0ull, 0ull, 0ull};
#pragma unroll 8
    for (int j = 0; j < 64; ++j) {
        float p = ps[i][j];
        u64 pp = pack2(p, p);
        float4 v0 = *(const float4*)&vs[j][e0];
        float4 v1 = *(const float4*)&vs[j][e0 + 4];
        ffma2(o2[0], pp, pack2(v0.x, v0.y));
        ffma2(o2[1], pp, pack2(v0.z, v0.w));
        ffma2(o2[2], pp, pack2(v1.x, v1.y));
        ffma2(o2[3], pp, pack2(v1.z, v1.w));
    }
    float2 r0 = unpack2(o2[0]), r1 = unpack2(o2[1]);
    float2 r2 = unpack2(o2[2]), r3 = unpack2(o2[3]);
    float* cp = &g_ctx[((size_t)win * D + i) * C + h * 32 + e0];
    *(float4*)cp       = make_float4(r0.x, r0.y, r1.x, r1.y);
    *(float4*)(cp + 4) = make_float4(r2.x, r2.y, r3.x, r3.y);
}

// ---------------------------------------------------------------------------
// Kernel 3: output projection + window-reverse + roll(+4,+4) scatter.
// grid = (3, 1024), 2 windows per CTA.
// ---------------------------------------------------------------------------
__global__ __launch_bounds__(256, 2) void proj_kernel(
    const float* __restrict__ w, const float* __restrict__ bias,
    float* __restrict__ out)
{
    __shared__ float2 As2[128][32];
    __shared__ float  Bs[32][128];
    const int tid = threadIdx.x;
    const int wpair = blockIdx.y;
    const int n0  = blockIdx.x * 128;

    const int arow0 = tid >> 3;
    const int arow1 = arow0 + 32, arow2 = arow0 + 64, arow3 = arow0 + 96;
    const float* abase = &g_ctx[(size_t)wpair * 128 * C];
    const float* ap0 = abase + (size_t)arow0 * C;
    const float* ap1 = abase + (size_t)arow1 * C;
    const float* ap2 = abase + (size_t)arow2 * C;
    const float* ap3 = abase + (size_t)arow3 * C;

    u64 acc2[8][4];
#pragma unroll
    for (int i = 0; i < 8; ++i)
#pragma unroll
        for (int j = 0; j < 4; ++j) acc2[i][j] = 0ull;

    gemm_body(ap0, ap1, ap2, ap3, arow0, arow1, arow2, arow3,
              w, C, n0, tid, acc2, As2, Bs);

    const int tn8 = (tid & 15) << 3;
    const int tm8 = (tid >> 4) << 3;
    const float4 bb0 = *(const float4*)&bias[n0 + tn8];
    const float4 bb1 = *(const float4*)&bias[n0 + tn8 + 4];
#pragma unroll
    for (int i = 0; i < 8; ++i) {
        int row = tm8 + i;
        int win = wpair * 2 + (row >> 6);
        int img = win >> 6, wi = win & 63, wr = wi >> 3, wc = wi & 7;
        int t = row & 63, ri = t >> 3, ci = t & 7;
        int gr = (wr * 8 + ri + 4) & 63;   // window-reverse + roll(+4) == +4 mod 64
        int gc = (wc * 8 + ci + 4) & 63;
        float* op = out + (((size_t)img * 64 + gr) * 64 + gc) * C + n0 + tn8;
        float2 a0 = unpack2(acc2[i][0]);
        float2 a1 = unpack2(acc2[i][1]);
        float2 a2 = unpack2(acc2[i][2]);
        float2 a3 = unpack2(acc2[i][3]);
        *(float4*)op       = make_float4(a0.x + bb0.x, a0.y + bb0.y,
                                         a1.x + bb0.z, a1.y + bb0.w);
        *(float4*)(op + 4) = make_float4(a2.x + bb1.x, a2.y + bb1.y,
                                         a3.x + bb1.z, a3.y + bb1.w);
    }
}

// ---------------------------------------------------------------------------
extern "C" void kernel_launch(void* const* d_in, const int* in_sizes, int n_in,
                              void* d_out, int out_size)
{
    (void)in_sizes; (void)n_in; (void)out_size;
    const float* x      = (const float*)d_in[0];
    const float* w_qkv  = (const float*)d_in[1];
    const float* b_qkv  = (const float*)d_in[2];
    const float* w_out  = (const float*)d_in[3];
    const float* b_out  = (const float*)d_in[4];
    const float* btab   = (const float*)d_in[5];
    float* out = (float*)d_out;

    qkv_kernel <<<dim3(9, NWIN / 2),  256>>>(x, w_qkv, b_qkv);
    attn_kernel<<<dim3(NWIN, 12), 256>>>(btab);
    proj_kernel<<<dim3(3, NWIN / 2),  256>>>(w_out, b_out, out);
}

// round 5
// speedup vs baseline: 1.5799x; 1.5799x over previous
#include <cuda_runtime.h>
#include <cuda_bf16.h>
#include <cstdint>

#define C        384
#define NQKV     1152
#define NWIN     2048   // 32 images * 64 windows
#define D        64     // tokens per window
#define KCH      64     // K per smem chunk
#define NCHUNK   (C / KCH)   // 6

// Dynamic smem layout: 4 bf16 tiles [128][64] (A_hi, A_lo, B_hi, B_lo),
// then reused as f32 restage S[128][132].
#define SM_AHI   0
#define SM_ALO   16384
#define SM_BHI   32768
#define SM_BLO   49152
#define SMEM_BYTES 67584   // max(65536, 128*132*4)

// ---------------------------------------------------------------------------
// Scratch (device globals are the sanctioned scratch mechanism).
__device__ float          g_qkv[(size_t)NWIN * D * NQKV];   // fp32 qkv
__device__ float          g_ctx[(size_t)NWIN * D * C];      // fp32 attn out
__device__ __nv_bfloat16  g_wqkv_hi[(size_t)NQKV * C];      // W_qkv^T hi [n][k]
__device__ __nv_bfloat16  g_wqkv_lo[(size_t)NQKV * C];
__device__ __nv_bfloat16  g_wout_hi[(size_t)C * C];         // W_out^T hi [n][k]
__device__ __nv_bfloat16  g_wout_lo[(size_t)C * C];

// ---------------------------------------------------------------------------
typedef unsigned long long u64;
__device__ __forceinline__ u64 pack2(float a, float b) {
    u64 r; asm("mov.b64 %0, {%1, %2};" : "=l"(r) : "f"(a), "f"(b)); return r;
}
__device__ __forceinline__ void ffma2(u64& d, u64 a, u64 b) {
    asm("fma.rn.f32x2 %0, %1, %2, %0;" : "+l"(d) : "l"(a), "l"(b));
}
__device__ __forceinline__ float2 unpack2(u64 v) {
    float x, y; asm("mov.b64 {%0, %1}, %2;" : "=f"(x), "=f"(y) : "l"(v));
    return make_float2(x, y);
}
__device__ __forceinline__ uint32_t smem_u32(const void* p) {
    uint32_t a;
    asm("{ .reg .u64 t; cvta.to.shared.u64 t, %1; cvt.u32.u64 %0, t; }"
        : "=r"(a) : "l"(p));
    return a;
}
__device__ __forceinline__ void ldsm4(uint32_t r[4], uint32_t addr) {
    asm volatile("ldmatrix.sync.aligned.m8n8.x4.shared.b16 {%0,%1,%2,%3}, [%4];"
                 : "=r"(r[0]), "=r"(r[1]), "=r"(r[2]), "=r"(r[3]) : "r"(addr));
}
__device__ __forceinline__ void mma16816(float d[4], const uint32_t a[4],
                                         const uint32_t b[2]) {
    asm volatile(
        "mma.sync.aligned.m16n8k16.row.col.f32.bf16.bf16.f32 "
        "{%0,%1,%2,%3}, {%4,%5,%6,%7}, {%8,%9}, {%0,%1,%2,%3};"
        : "+f"(d[0]), "+f"(d[1]), "+f"(d[2]), "+f"(d[3])
        : "r"(a[0]), "r"(a[1]), "r"(a[2]), "r"(a[3]), "r"(b[0]), "r"(b[1]));
}
__device__ __forceinline__ void split_bf16(float v, uint16_t& h, uint16_t& l) {
    __nv_bfloat16 hb = __float2bfloat16(v);
    __nv_bfloat16 lb = __float2bfloat16(v - __bfloat162float(hb));
    h = __bfloat16_as_ushort(hb);
    l = __bfloat16_as_ushort(lb);
}
// Swizzled byte offset within a [128 rows x 128 bytes] tile (16B granules).
__device__ __forceinline__ uint32_t swz(int row, int colbyte) {
    return (uint32_t)(row * 128 + (colbyte ^ ((row & 7) << 4)));
}

// ---------------------------------------------------------------------------
// Weight prep: transpose + bf16 hi/lo split.  Wt[n][k] = split(W[k][n]).
// ---------------------------------------------------------------------------
__global__ void prep_wqkv(const float* __restrict__ w) {
    int lin = blockIdx.x * 256 + threadIdx.x;       // 1152*96 threads
    int k4 = (lin % 96) * 4;
    int n  = lin / 96;
    uint16_t h[4], l[4];
#pragma unroll
    for (int j = 0; j < 4; ++j) split_bf16(w[(size_t)(k4 + j) * NQKV + n], h[j], l[j]);
    *(uint2*)&g_wqkv_hi[(size_t)n * C + k4] =
        make_uint2((uint32_t)h[0] | ((uint32_t)h[1] << 16),
                   (uint32_t)h[2] | ((uint32_t)h[3] << 16));
    *(uint2*)&g_wqkv_lo[(size_t)n * C + k4] =
        make_uint2((uint32_t)l[0] | ((uint32_t)l[1] << 16),
                   (uint32_t)l[2] | ((uint32_t)l[3] << 16));
}
__global__ void prep_wout(const float* __restrict__ w) {
    int lin = blockIdx.x * 256 + threadIdx.x;       // 384*96 threads
    int k4 = (lin % 96) * 4;
    int n  = lin / 96;
    uint16_t h[4], l[4];
#pragma unroll
    for (int j = 0; j < 4; ++j) split_bf16(w[(size_t)(k4 + j) * C + n], h[j], l[j]);
    *(uint2*)&g_wout_hi[(size_t)n * C + k4] =
        make_uint2((uint32_t)h[0] | ((uint32_t)h[1] << 16),
                   (uint32_t)h[2] | ((uint32_t)h[3] << 16));
    *(uint2*)&g_wout_lo[(size_t)n * C + k4] =
        make_uint2((uint32_t)l[0] | ((uint32_t)l[1] << 16),
                   (uint32_t)l[2] | ((uint32_t)l[3] << 16));
}

// Map row 0..127 of a 2-window CTA to the gathered x pointer (roll -4).
__device__ __forceinline__ const float* qkv_row_ptr(const float* x, int wpair, int row) {
    int win = wpair * 2 + (row >> 6);
    int img = win >> 6, wi = win & 63, wr = wi >> 3, wc = wi & 7;
    int t = row & 63, ri = t >> 3, ci = t & 7;
    int gr = (wr * 8 + ri + 4) & 63;
    int gc = (wc * 8 + ci + 4) & 63;
    return x + (((size_t)img * 64 + gr) * 64 + gc) * C;
}

// ---------------------------------------------------------------------------
// Shared GEMM body: acc[128,128] (f32) = split3-bf16 A[128,384] x B^T[128n,384k]
// ap[u]: per-thread fp32 A row pointers (+ g*8); bph/bpl: bf16 B row pointers.
// ---------------------------------------------------------------------------
__device__ __forceinline__ void gemm_mma(
    char* smem, uint32_t sb, int tid,
    const float* ap[4], const __nv_bfloat16* bph[4], const __nv_bfloat16* bpl[4],
    const uint32_t swa[4], float acc[4][4][4])
{
    const int lane = tid & 31, wid = tid >> 5;
    const int wm = (wid & 1) * 64;
    const int wn = (wid >> 1) * 32;
    const int r8 = lane & 7, mat = lane >> 3;
    const int colh = (mat >> 1) * 16;           // 0 or 16 bytes

    // Per-thread ldmatrix row bases
    uint32_t abase[4], bbase[2];
#pragma unroll
    for (int mi = 0; mi < 4; ++mi) {
        int row = wm + mi * 16 + (mat & 1) * 8 + r8;
        abase[mi] = sb + (uint32_t)(row * 128) + ((uint32_t)((row & 7) << 4));
        // swizzle of colh^... handled at use: addr = base_row ^ adjustments
    }
#pragma unroll
    for (int np = 0; np < 2; ++np) {
        int row = wn + np * 16 + (mat & 1) * 8 + r8;
        bbase[np] = sb + (uint32_t)(row * 128) + ((uint32_t)((row & 7) << 4));
    }
    // NOTE: swz(row, c) = row*128 + (c ^ ((row&7)<<4)). Since (row&7)<<4 has
    // only bits 4-6 and c is a multiple of 16 < 128, XOR == add of XORed col:
    // addr = sb + row*128 + (c ^ sw). We precomputed sb + row*128 + sw; the
    // remaining col must be XORed into bits 4-6: (sw ^ (c ^ sw)) ... simplest:
    // recompute addr = rowterm + (c ^ swbits) - swbits + swbits. To stay exact
    // we instead store rowterm = sb + row*128 and swbits separately below.

    uint32_t arow[4], asw[4], brow[2], bsw[2];
#pragma unroll
    for (int mi = 0; mi < 4; ++mi) {
        int row = wm + mi * 16 + (mat & 1) * 8 + r8;
        arow[mi] = sb + (uint32_t)(row * 128);
        asw[mi]  = (uint32_t)((row & 7) << 4);
    }
#pragma unroll
    for (int np = 0; np < 2; ++np) {
        int row = wn + np * 16 + (mat & 1) * 8 + r8;
        brow[np] = sb + (uint32_t)(row * 128);
        bsw[np]  = (uint32_t)((row & 7) << 4);
    }

    for (int it = 0; it < NCHUNK; ++it) {
        const int k0 = it * KCH;
        // ---- stage A (fp32 -> bf16 hi/lo) and B (preconverted) ----
#pragma unroll
        for (int u = 0; u < 4; ++u) {
            const float* p = ap[u] + k0;
            float4 v0 = *(const float4*)p;
            float4 v1 = *(const float4*)(p + 4);
            uint16_t h[8], l[8];
            split_bf16(v0.x, h[0], l[0]); split_bf16(v0.y, h[1], l[1]);
            split_bf16(v0.z, h[2], l[2]); split_bf16(v0.w, h[3], l[3]);
            split_bf16(v1.x, h[4], l[4]); split_bf16(v1.y, h[5], l[5]);
            split_bf16(v1.z, h[6], l[6]); split_bf16(v1.w, h[7], l[7]);
            *(uint4*)(smem + SM_AHI + swa[u]) =
                make_uint4((uint32_t)h[0] | ((uint32_t)h[1] << 16),
                           (uint32_t)h[2] | ((uint32_t)h[3] << 16),
                           (uint32_t)h[4] | ((uint32_t)h[5] << 16),
                           (uint32_t)h[6] | ((uint32_t)h[7] << 16));
            *(uint4*)(smem + SM_ALO + swa[u]) =
                make_uint4((uint32_t)l[0] | ((uint32_t)l[1] << 16),
                           (uint32_t)l[2] | ((uint32_t)l[3] << 16),
                           (uint32_t)l[4] | ((uint32_t)l[5] << 16),
                           (uint32_t)l[6] | ((uint32_t)l[7] << 16));
            *(uint4*)(smem + SM_BHI + swa[u]) = *(const uint4*)(bph[u] + k0);
            *(uint4*)(smem + SM_BLO + swa[u]) = *(const uint4*)(bpl[u] + k0);
        }
        __syncthreads();

        // ---- mma over 4 k16 steps ----
#pragma unroll
        for (int ks = 0; ks < 4; ++ks) {
            const uint32_t cb = (uint32_t)(ks * 32 + colh);
            uint32_t a[4][4], bh[4][2], bl[4][2];
#pragma unroll
            for (int mi = 0; mi < 4; ++mi)
                ldsm4(a[mi], arow[mi] + SM_AHI + (cb ^ asw[mi]));
#pragma unroll
            for (int np = 0; np < 2; ++np) {
                uint32_t t[4];
                ldsm4(t, brow[np] + SM_BHI + (cb ^ bsw[np]));
                bh[np * 2][0] = t[0]; bh[np * 2 + 1][0] = t[1];
                bh[np * 2][1] = t[2]; bh[np * 2 + 1][1] = t[3];
                ldsm4(t, brow[np] + SM_BLO + (cb ^ bsw[np]));
                bl[np * 2][0] = t[0]; bl[np * 2 + 1][0] = t[1];
                bl[np * 2][1] = t[2]; bl[np * 2 + 1][1] = t[3];
            }
#pragma unroll
            for (int mi = 0; mi < 4; ++mi)
#pragma unroll
                for (int ni = 0; ni < 4; ++ni) {
                    mma16816(acc[mi][ni], a[mi], bh[ni]);
                    mma16816(acc[mi][ni], a[mi], bl[ni]);
                }
#pragma unroll
            for (int mi = 0; mi < 4; ++mi)
                ldsm4(a[mi], arow[mi] + SM_ALO + (cb ^ asw[mi]));
#pragma unroll
            for (int mi = 0; mi < 4; ++mi)
#pragma unroll
                for (int ni = 0; ni < 4; ++ni)
                    mma16816(acc[mi][ni], a[mi], bh[ni]);
        }
        __syncthreads();
    }
}

// Store acc fragments into restage smem S[128][132].
__device__ __forceinline__ void acc_to_smem(float (*S)[132], int tid,
                                            float acc[4][4][4])
{
    const int lane = tid & 31, wid = tid >> 5;
    const int wm = (wid & 1) * 64;
    const int wn = (wid >> 1) * 32;
    const int er = lane >> 2, ec = (lane & 3) * 2;
#pragma unroll
    for (int mi = 0; mi < 4; ++mi)
#pragma unroll
        for (int ni = 0; ni < 4; ++ni) {
            float* d = acc[mi][ni];
            *(float2*)&S[wm + mi * 16 + er][wn + ni * 8 + ec] =
                make_float2(d[0], d[1]);
            *(float2*)&S[wm + mi * 16 + 8 + er][wn + ni * 8 + ec] =
                make_float2(d[2], d[3]);
        }
}

// ---------------------------------------------------------------------------
// Kernel 1: QKV. grid = (9, 1024), 256 threads. Output fp32 g_qkv.
// ---------------------------------------------------------------------------
__global__ __launch_bounds__(256) void qkv_mma(
    const float* __restrict__ x, const float* __restrict__ bias)
{
    extern __shared__ char smem[];
    const uint32_t sb = smem_u32(smem);
    const int tid = threadIdx.x;
    const int wpair = blockIdx.y;
    const int n0 = blockIdx.x * 128;

    const int g = tid & 7;
    const float* ap[4];
    const __nv_bfloat16* bph[4];
    const __nv_bfloat16* bpl[4];
    uint32_t swa[4];
#pragma unroll
    for (int u = 0; u < 4; ++u) {
        int row = (tid >> 3) + 32 * u;
        ap[u]  = qkv_row_ptr(x, wpair, row) + g * 8;
        bph[u] = g_wqkv_hi + (size_t)(n0 + row) * C + g * 8;
        bpl[u] = g_wqkv_lo + (size_t)(n0 + row) * C + g * 8;
        swa[u] = swz(row, g * 16);
    }

    float acc[4][4][4];
#pragma unroll
    for (int mi = 0; mi < 4; ++mi)
#pragma unroll
        for (int ni = 0; ni < 4; ++ni)
#pragma unroll
            for (int q = 0; q < 4; ++q) acc[mi][ni][q] = 0.f;

    gemm_mma(smem, sb, tid, ap, bph, bpl, swa, acc);

    float (*S)[132] = (float(*)[132])smem;
    acc_to_smem(S, tid, acc);
    __syncthreads();

    const int lid = tid & 31, wid = tid >> 5;
    const float4 bb = *(const float4*)&bias[n0 + lid * 4];
#pragma unroll
    for (int p = 0; p < 16; ++p) {
        int row = p * 8 + wid;
        float4 v = *(const float4*)&S[row][lid * 4];
        v.x += bb.x; v.y += bb.y; v.z += bb.z; v.w += bb.w;
        size_t m = (size_t)wpair * 128 + row;
        *(float4*)&g_qkv[m * NQKV + n0 + lid * 4] = v;
    }
}

// ---------------------------------------------------------------------------
// Kernel 2: attention per (window, head). grid = (2048, 12), 256 threads.
// ---------------------------------------------------------------------------
__global__ __launch_bounds__(256) void attn_kernel(const float* __restrict__ bt)
{
    __shared__ float qs[64][32];
    __shared__ float ks[64][36];
    __shared__ float vs[64][36];
    __shared__ float ps[64][68];
    __shared__ int   s_sum[64];
    __shared__ int   s_regn[64];
    __shared__ float s_bias[32];

    const int tid = threadIdx.x;
    const int win = blockIdx.x;
    const int h   = blockIdx.y;
    const float scale = 0.17677669529663687f;  // 1/sqrt(32)

    if (tid < 64) {
        int wi = win & 63, wr = wi >> 3, wc = wi & 7;
        int ri = tid >> 3, ci = tid & 7;
        s_sum[tid] = ri + ci;
        int gr = wr * 8 + ri, gc = wc * 8 + ci;
        int rb = gr < 56 ? 0 : (gr < 60 ? 1 : 2);
        int cb = gc < 56 ? 0 : (gc < 60 ? 1 : 2);
        s_regn[tid] = rb * 3 + cb;
    }
    if (tid >= 64 && tid < 93) {
        int u = tid - 64;                    // bias idx range is [15, 43]
        s_bias[u] = bt[(u + 15) * 12 + h];
    }

    const size_t base = ((size_t)win * D) * NQKV + (size_t)h * 32;
#pragma unroll
    for (int s = 0; s < 2; ++s) {
        int slot = tid + 256 * s;
        int row  = slot >> 3;
        int eq   = (slot & 7) << 2;
        const float* src = &g_qkv[base + (size_t)row * NQKV + eq];
        float4 q4 = *(const float4*)(src);
        q4.x *= scale; q4.y *= scale; q4.z *= scale; q4.w *= scale;
        *(float4*)&qs[row][eq] = q4;
        *(float4*)&ks[row][eq] = *(const float4*)(src + 384);
        *(float4*)&vs[row][eq] = *(const float4*)(src + 768);
    }
    __syncthreads();

    const int i  = tid >> 2;   // query row, 4 threads per row
    const int jg = tid & 3;
    u64 q2[16];
#pragma unroll
    for (int e = 0; e < 32; e += 4) {
        float4 qq = *(const float4*)&qs[i][e];
        q2[(e >> 1)]     = pack2(qq.x, qq.y);
        q2[(e >> 1) + 1] = pack2(qq.z, qq.w);
    }
    const int isum  = s_sum[i];
    const int iregn = s_regn[i];

    float sc[16];
    float mx = -1e30f;
#pragma unroll
    for (int jj = 0; jj < 16; ++jj) {
        int j = (jj << 2) + jg;
        u64 acc2 = 0ull;
#pragma unroll
        for (int e = 0; e < 32; e += 4) {
            float4 k4 = *(const float4*)&ks[j][e];
            ffma2(acc2, q2[(e >> 1)],     pack2(k4.x, k4.y));
            ffma2(acc2, q2[(e >> 1) + 1], pack2(k4.z, k4.w));
        }
        float2 apn = unpack2(acc2);
        float acc = apn.x + apn.y;
        acc += s_bias[isum - s_sum[j] + 14];
        if (iregn != s_regn[j]) acc -= 100.f;
        sc[jj] = acc;
        mx = fmaxf(mx, acc);
    }
    mx = fmaxf(mx, __shfl_xor_sync(0xffffffffu, mx, 1));
    mx = fmaxf(mx, __shfl_xor_sync(0xffffffffu, mx, 2));

    float sum = 0.f;
#pragma unroll
    for (int jj = 0; jj < 16; ++jj) {
        float e = __expf(sc[jj] - mx);
        sc[jj] = e;
        sum += e;
    }
    sum += __shfl_xor_sync(0xffffffffu, sum, 1);
    sum += __shfl_xor_sync(0xffffffffu, sum, 2);
    float inv = 1.f / sum;
#pragma unroll
    for (int jj = 0; jj < 16; ++jj) ps[i][(jj << 2) + jg] = sc[jj] * inv;
    __syncthreads();

    const int e0 = (tid & 3) << 3;
    u64 o2[4] = {0ull, 0ull, 0ull, 0ull};
#pragma unroll 8
    for (int j = 0; j < 64; ++j) {
        float p = ps[i][j];
        u64 pp = pack2(p, p);
        float4 v0 = *(const float4*)&vs[j][e0];
        float4 v1 = *(const float4*)&vs[j][e0 + 4];
        ffma2(o2[0], pp, pack2(v0.x, v0.y));
        ffma2(o2[1], pp, pack2(v0.z, v0.w));
        ffma2(o2[2], pp, pack2(v1.x, v1.y));
        ffma2(o2[3], pp, pack2(v1.z, v1.w));
    }
    float2 r0 = unpack2(o2[0]), r1 = unpack2(o2[1]);
    float2 r2 = unpack2(o2[2]), r3 = unpack2(o2[3]);
    float* cp = &g_ctx[((size_t)win * D + i) * C + h * 32 + e0];
    *(float4*)cp       = make_float4(r0.x, r0.y, r1.x, r1.y);
    *(float4*)(cp + 4) = make_float4(r2.x, r2.y, r3.x, r3.y);
}

// ---------------------------------------------------------------------------
// Kernel 3: projection + window-reverse/roll scatter. grid = (3, 1024).
// ---------------------------------------------------------------------------
__global__ __launch_bounds__(256) void proj_mma(
    const float* __restrict__ bias, float* __restrict__ out)
{
    extern __shared__ char smem[];
    const uint32_t sb = smem_u32(smem);
    const int tid = threadIdx.x;
    const int wpair = blockIdx.y;
    const int n0 = blockIdx.x * 128;

    const int g = tid & 7;
    const float* ap[4];
    const __nv_bfloat16* bph[4];
    const __nv_bfloat16* bpl[4];
    uint32_t swa[4];
#pragma unroll
    for (int u = 0; u < 4; ++u) {
        int row = (tid >> 3) + 32 * u;
        ap[u]  = g_ctx + ((size_t)wpair * 128 + row) * C + g * 8;
        bph[u] = g_wout_hi + (size_t)(n0 + row) * C + g * 8;
        bpl[u] = g_wout_lo + (size_t)(n0 + row) * C + g * 8;
        swa[u] = swz(row, g * 16);
    }

    float acc[4][4][4];
#pragma unroll
    for (int mi = 0; mi < 4; ++mi)
#pragma unroll
        for (int ni = 0; ni < 4; ++ni)
#pragma unroll
            for (int q = 0; q < 4; ++q) acc[mi][ni][q] = 0.f;

    gemm_mma(smem, sb, tid, ap, bph, bpl, swa, acc);

    float (*S)[132] = (float(*)[132])smem;
    acc_to_smem(S, tid, acc);
    __syncthreads();

    const int lid = tid & 31, wid = tid >> 5;
    const float4 bb = *(const float4*)&bias[n0 + lid * 4];
#pragma unroll
    for (int p = 0; p < 16; ++p) {
        int row = p * 8 + wid;
        float4 v = *(const float4*)&S[row][lid * 4];
        v.x += bb.x; v.y += bb.y; v.z += bb.z; v.w += bb.w;
        int tok = wpair * 128 + row;
        int win = tok >> 6;
        int img = win >> 6, wi = win & 63, wr = wi >> 3, wc = wi & 7;
        int t = tok & 63, ri = t >> 3, ci = t & 7;
        int gr = (wr * 8 + ri + 4) & 63;   // window-reverse + roll(+4) == +4 mod 64
        int gc = (wc * 8 + ci + 4) & 63;
        *(float4*)(out + (((size_t)img * 64 + gr) * 64 + gc) * C + n0 + lid * 4) = v;
    }
}

// ---------------------------------------------------------------------------
namespace {
struct ForceLoad {
    ForceLoad() {
        void* p = nullptr;
        cudaGetSymbolAddress(&p, g_qkv);
        cudaGetSymbolAddress(&p, g_ctx);
        cudaFuncSetAttribute(qkv_mma,  cudaFuncAttributeMaxDynamicSharedMemorySize, SMEM_BYTES);
        cudaFuncSetAttribute(proj_mma, cudaFuncAttributeMaxDynamicSharedMemorySize, SMEM_BYTES);
    }
};
ForceLoad g_force_load;
}

extern "C" void kernel_launch(void* const* d_in, const int* in_sizes, int n_in,
                              void* d_out, int out_size)
{
    (void)in_sizes; (void)n_in; (void)out_size;
    const float* x      = (const float*)d_in[0];
    const float* w_qkv  = (const float*)d_in[1];
    const float* b_qkv  = (const float*)d_in[2];
    const float* w_out  = (const float*)d_in[3];
    const float* b_out  = (const float*)d_in[4];
    const float* btab   = (const float*)d_in[5];
    float* out = (float*)d_out;

    prep_wqkv<<<432, 256>>>(w_qkv);
    prep_wout<<<144, 256>>>(w_out);
    qkv_mma  <<<dim3(9, NWIN / 2), 256, SMEM_BYTES>>>(x, b_qkv);
    attn_kernel<<<dim3(NWIN, 12), 256>>>(btab);
    proj_mma <<<dim3(3, NWIN / 2), 256, SMEM_BYTES>>>(b_out, out);
}

// round 6
// speedup vs baseline: 2.5304x; 1.6016x over previous
#include <cuda_runtime.h>
#include <cuda_bf16.h>
#include <cstdint>

#define C        384
#define NQKV     1152
#define NWIN     2048   // 32 images * 64 windows
#define D        64     // tokens per window
#define KCH      32     // K per pipeline chunk
#define NCHUNK   (C / KCH)   // 12

// GEMM smem tiles (bf16 [128][32] = 8KB each), two stages
#define SA_HI 0
#define SA_LO 8192
#define SB_HI 16384
#define SB_LO 24576
#define STAGE_STRIDE 32768
#define SMEM_BYTES 67584   // max(2*32768, 128*132*4)

// ---------------------------------------------------------------------------
// Scratch (device globals are the sanctioned scratch mechanism).
__device__ __nv_bfloat16 g_x_hi[(size_t)32 * 64 * 64 * C];
__device__ __nv_bfloat16 g_x_lo[(size_t)32 * 64 * 64 * C];
__device__ __nv_bfloat16 g_qkv_hi[(size_t)NWIN * D * NQKV];
__device__ __nv_bfloat16 g_qkv_lo[(size_t)NWIN * D * NQKV];
__device__ __nv_bfloat16 g_ctx_hi[(size_t)NWIN * D * C];
__device__ __nv_bfloat16 g_ctx_lo[(size_t)NWIN * D * C];
__device__ __nv_bfloat16 g_wqkv_hi[(size_t)NQKV * C];   // W^T [n][k]
__device__ __nv_bfloat16 g_wqkv_lo[(size_t)NQKV * C];
__device__ __nv_bfloat16 g_wout_hi[(size_t)C * C];
__device__ __nv_bfloat16 g_wout_lo[(size_t)C * C];

// ---------------------------------------------------------------------------
__device__ __forceinline__ uint32_t smem_u32(const void* p) {
    uint32_t a;
    asm("{ .reg .u64 t; cvta.to.shared.u64 t, %1; cvt.u32.u64 %0, t; }"
        : "=r"(a) : "l"(p));
    return a;
}
__device__ __forceinline__ void cp16(uint32_t d, const void* s) {
    asm volatile("cp.async.ca.shared.global [%0], [%1], 16;" :: "r"(d), "l"(s));
}
#define CP_COMMIT() asm volatile("cp.async.commit_group;" ::: "memory")
#define CP_WAIT0()  asm volatile("cp.async.wait_group 0;" ::: "memory")
#define CP_WAIT1()  asm volatile("cp.async.wait_group 1;" ::: "memory")

__device__ __forceinline__ void ldsm4(uint32_t r[4], uint32_t addr) {
    asm volatile("ldmatrix.sync.aligned.m8n8.x4.shared.b16 {%0,%1,%2,%3}, [%4];"
                 : "=r"(r[0]), "=r"(r[1]), "=r"(r[2]), "=r"(r[3]) : "r"(addr));
}
__device__ __forceinline__ void ldsm4t(uint32_t r[4], uint32_t addr) {
    asm volatile("ldmatrix.sync.aligned.m8n8.x4.trans.shared.b16 {%0,%1,%2,%3}, [%4];"
                 : "=r"(r[0]), "=r"(r[1]), "=r"(r[2]), "=r"(r[3]) : "r"(addr));
}
__device__ __forceinline__ void mma16816(float d[4], const uint32_t a[4],
                                         const uint32_t b[2]) {
    asm volatile(
        "mma.sync.aligned.m16n8k16.row.col.f32.bf16.bf16.f32 "
        "{%0,%1,%2,%3}, {%4,%5,%6,%7}, {%8,%9}, {%0,%1,%2,%3};"
        : "+f"(d[0]), "+f"(d[1]), "+f"(d[2]), "+f"(d[3])
        : "r"(a[0]), "r"(a[1]), "r"(a[2]), "r"(a[3]), "r"(b[0]), "r"(b[1]));
}
__device__ __forceinline__ void split_bf16(float v, uint16_t& h, uint16_t& l) {
    __nv_bfloat16 hb = __float2bfloat16(v);
    __nv_bfloat16 lb = __float2bfloat16(v - __bfloat162float(hb));
    h = __bfloat16_as_ushort(hb);
    l = __bfloat16_as_ushort(lb);
}
__device__ __forceinline__ uint32_t pack_hi2(float a, float b) {
    uint16_t ha, la, hb, lb;
    split_bf16(a, ha, la); split_bf16(b, hb, lb);
    return (uint32_t)ha | ((uint32_t)hb << 16);
}
// 64-byte-row swizzle: granule col ^= (row>>1)&3  (conflict-free for ldsm/STS/cp)
__device__ __forceinline__ uint32_t sw64(int row, int cg) {
    return (uint32_t)(row * 64 + ((cg ^ ((row >> 1) & 3)) << 4));
}

// ---------------------------------------------------------------------------
// Prep kernels: splits to bf16 hi/lo (+ transpose for weights).
// ---------------------------------------------------------------------------
__global__ void prep_x(const float* __restrict__ x) {
    size_t i4 = ((size_t)blockIdx.x * 256 + threadIdx.x) * 4;
    float4 v = *(const float4*)(x + i4);
    uint16_t h[4], l[4];
    split_bf16(v.x, h[0], l[0]); split_bf16(v.y, h[1], l[1]);
    split_bf16(v.z, h[2], l[2]); split_bf16(v.w, h[3], l[3]);
    *(uint2*)&g_x_hi[i4] = make_uint2((uint32_t)h[0] | ((uint32_t)h[1] << 16),
                                      (uint32_t)h[2] | ((uint32_t)h[3] << 16));
    *(uint2*)&g_x_lo[i4] = make_uint2((uint32_t)l[0] | ((uint32_t)l[1] << 16),
                                      (uint32_t)l[2] | ((uint32_t)l[3] << 16));
}
__global__ void prep_wqkv(const float* __restrict__ w) {
    int lin = blockIdx.x * 256 + threadIdx.x;
    int k4 = (lin % 96) * 4;
    int n  = lin / 96;
    uint16_t h[4], l[4];
#pragma unroll
    for (int j = 0; j < 4; ++j) split_bf16(w[(size_t)(k4 + j) * NQKV + n], h[j], l[j]);
    *(uint2*)&g_wqkv_hi[(size_t)n * C + k4] =
        make_uint2((uint32_t)h[0] | ((uint32_t)h[1] << 16),
                   (uint32_t)h[2] | ((uint32_t)h[3] << 16));
    *(uint2*)&g_wqkv_lo[(size_t)n * C + k4] =
        make_uint2((uint32_t)l[0] | ((uint32_t)l[1] << 16),
                   (uint32_t)l[2] | ((uint32_t)l[3] << 16));
}
__global__ void prep_wout(const float* __restrict__ w) {
    int lin = blockIdx.x * 256 + threadIdx.x;
    int k4 = (lin % 96) * 4;
    int n  = lin / 96;
    uint16_t h[4], l[4];
#pragma unroll
    for (int j = 0; j < 4; ++j) split_bf16(w[(size_t)(k4 + j) * C + n], h[j], l[j]);
    *(uint2*)&g_wout_hi[(size_t)n * C + k4] =
        make_uint2((uint32_t)h[0] | ((uint32_t)h[1] << 16),
                   (uint32_t)h[2] | ((uint32_t)h[3] << 16));
    *(uint2*)&g_wout_lo[(size_t)n * C + k4] =
        make_uint2((uint32_t)l[0] | ((uint32_t)l[1] << 16),
                   (uint32_t)l[2] | ((uint32_t)l[3] << 16));
}

// Gathered token index (roll -4 + window partition) for qkv A rows.
__device__ __forceinline__ size_t qkv_row_off(int wpair, int row) {
    int win = wpair * 2 + (row >> 6);
    int img = win >> 6, wi = win & 63, wr = wi >> 3, wc = wi & 7;
    int t = row & 63, ri = t >> 3, ci = t & 7;
    int gr = (wr * 8 + ri + 4) & 63;
    int gc = (wc * 8 + ci + 4) & 63;
    return (((size_t)img * 64 + gr) * 64 + gc) * C;
}

// ---------------------------------------------------------------------------
// GEMM mma on one staged chunk (KCH=32, 2 k16 steps). 8 warps, 128x128 acc.
// ---------------------------------------------------------------------------
__device__ __forceinline__ void mma_stage(uint32_t sbase, int lane, int wm, int wn,
                                          float acc[4][4][4])
{
    const int aro = (lane & 7) + ((lane >> 3) & 1) * 8;
    const int cgs = lane >> 4;
#pragma unroll
    for (int ks = 0; ks < 2; ++ks) {
        const int cg = ks * 2 + cgs;
        uint32_t bh[4][2], bl[4][2];
#pragma unroll
        for (int np = 0; np < 2; ++np) {
            int r = wn + np * 16 + aro;
            uint32_t bd = sbase + sw64(r, cg);
            uint32_t t[4];
            ldsm4(t, bd + SB_HI);
            bh[np*2][0] = t[0]; bh[np*2+1][0] = t[1];
            bh[np*2][1] = t[2]; bh[np*2+1][1] = t[3];
            ldsm4(t, bd + SB_LO);
            bl[np*2][0] = t[0]; bl[np*2+1][0] = t[1];
            bl[np*2][1] = t[2]; bl[np*2+1][1] = t[3];
        }
        uint32_t a[4][4];
#pragma unroll
        for (int mi = 0; mi < 4; ++mi)
            ldsm4(a[mi], sbase + SA_HI + sw64(wm + mi * 16 + aro, cg));
#pragma unroll
        for (int mi = 0; mi < 4; ++mi)
#pragma unroll
            for (int ni = 0; ni < 4; ++ni) {
                mma16816(acc[mi][ni], a[mi], bh[ni]);
                mma16816(acc[mi][ni], a[mi], bl[ni]);
            }
#pragma unroll
        for (int mi = 0; mi < 4; ++mi)
            ldsm4(a[mi], sbase + SA_LO + sw64(wm + mi * 16 + aro, cg));
#pragma unroll
        for (int mi = 0; mi < 4; ++mi)
#pragma unroll
            for (int ni = 0; ni < 4; ++ni)
                mma16816(acc[mi][ni], a[mi], bh[ni]);
    }
}

__device__ __forceinline__ void acc_to_smem(float (*S)[132], int tid,
                                            float acc[4][4][4])
{
    const int lane = tid & 31, wid = tid >> 5;
    const int wm = (wid & 1) * 64;
    const int wn = (wid >> 1) * 32;
    const int er = lane >> 2, ec = (lane & 3) * 2;
#pragma unroll
    for (int mi = 0; mi < 4; ++mi)
#pragma unroll
        for (int ni = 0; ni < 4; ++ni) {
            float* d = acc[mi][ni];
            *(float2*)&S[wm + mi*16 + er][wn + ni*8 + ec]     = make_float2(d[0], d[1]);
            *(float2*)&S[wm + mi*16 + 8 + er][wn + ni*8 + ec] = make_float2(d[2], d[3]);
        }
}

// ---------------------------------------------------------------------------
// Kernel 1: QKV. grid = (9, 1024), 256 threads. Writes g_qkv hi/lo bf16.
// ---------------------------------------------------------------------------
__global__ __launch_bounds__(256) void qkv_mma(const float* __restrict__ bias)
{
    extern __shared__ char smem[];
    const uint32_t sb = smem_u32(smem);
    const int tid = threadIdx.x, lane = tid & 31, wid = tid >> 5;
    const int wpair = blockIdx.y;
    const int n0 = blockIdx.x * 128;
    const int wm = (wid & 1) * 64, wn = (wid >> 1) * 32;

    // cp.async geometry: thread -> row=tid>>1, 2 granules cg0,cg0+1
    const int row = tid >> 1;
    const int cg0 = (tid & 1) * 2;
    const uint32_t d0 = sw64(row, cg0), d1 = sw64(row, cg0 + 1);
    const __nv_bfloat16* pAh = g_x_hi + qkv_row_off(wpair, row) + cg0 * 8;
    const __nv_bfloat16* pAl = g_x_lo + qkv_row_off(wpair, row) + cg0 * 8;
    const __nv_bfloat16* pBh = g_wqkv_hi + (size_t)(n0 + row) * C + cg0 * 8;
    const __nv_bfloat16* pBl = g_wqkv_lo + (size_t)(n0 + row) * C + cg0 * 8;

    float acc[4][4][4];
#pragma unroll
    for (int mi = 0; mi < 4; ++mi)
#pragma unroll
        for (int ni = 0; ni < 4; ++ni)
#pragma unroll
            for (int q = 0; q < 4; ++q) acc[mi][ni][q] = 0.f;

    // chunk 0
    {
        uint32_t s0 = sb;
        cp16(s0 + SA_HI + d0, pAh); cp16(s0 + SA_HI + d1, pAh + 8);
        cp16(s0 + SA_LO + d0, pAl); cp16(s0 + SA_LO + d1, pAl + 8);
        cp16(s0 + SB_HI + d0, pBh); cp16(s0 + SB_HI + d1, pBh + 8);
        cp16(s0 + SB_LO + d0, pBl); cp16(s0 + SB_LO + d1, pBl + 8);
        CP_COMMIT();
    }
    for (int it = 0; it < NCHUNK; ++it) {
        if (it + 1 < NCHUNK) {
            int k0 = (it + 1) * KCH;
            uint32_t s0 = sb + ((it + 1) & 1) * STAGE_STRIDE;
            cp16(s0 + SA_HI + d0, pAh + k0); cp16(s0 + SA_HI + d1, pAh + k0 + 8);
            cp16(s0 + SA_LO + d0, pAl + k0); cp16(s0 + SA_LO + d1, pAl + k0 + 8);
            cp16(s0 + SB_HI + d0, pBh + k0); cp16(s0 + SB_HI + d1, pBh + k0 + 8);
            cp16(s0 + SB_LO + d0, pBl + k0); cp16(s0 + SB_LO + d1, pBl + k0 + 8);
            CP_COMMIT();
            CP_WAIT1();
        } else {
            CP_WAIT0();
        }
        __syncthreads();
        mma_stage(sb + (it & 1) * STAGE_STRIDE, lane, wm, wn, acc);
        __syncthreads();
    }

    float (*S)[132] = (float(*)[132])smem;
    acc_to_smem(S, tid, acc);
    __syncthreads();

    const float4 bb = *(const float4*)&bias[n0 + lane * 4];
#pragma unroll
    for (int p = 0; p < 16; ++p) {
        int r = p * 8 + wid;
        float4 v = *(const float4*)&S[r][lane * 4];
        v.x += bb.x; v.y += bb.y; v.z += bb.z; v.w += bb.w;
        uint16_t h[4], l[4];
        split_bf16(v.x, h[0], l[0]); split_bf16(v.y, h[1], l[1]);
        split_bf16(v.z, h[2], l[2]); split_bf16(v.w, h[3], l[3]);
        size_t m = (size_t)wpair * 128 + r;
        *(uint2*)&g_qkv_hi[m * NQKV + n0 + lane * 4] =
            make_uint2((uint32_t)h[0] | ((uint32_t)h[1] << 16),
                       (uint32_t)h[2] | ((uint32_t)h[3] << 16));
        *(uint2*)&g_qkv_lo[m * NQKV + n0 + lane * 4] =
            make_uint2((uint32_t)l[0] | ((uint32_t)l[1] << 16),
                       (uint32_t)l[2] | ((uint32_t)l[3] << 16));
    }
}

// ---------------------------------------------------------------------------
// Kernel 2: flash-style HMMA attention. grid = (2048, 12), 128 threads.
// ---------------------------------------------------------------------------
#define AQH 0
#define AQL 4096
#define AKH 8192
#define AKL 12288
#define AVH 16384
#define AVL 20480

__global__ __launch_bounds__(128) void attn_mma(const float* __restrict__ bt)
{
    __shared__ char ts[24576];
    __shared__ float s_bias[32];
    const uint32_t sb = smem_u32(ts);
    const int tid = threadIdx.x, lane = tid & 31, w = tid >> 5;
    const int win = blockIdx.x, h = blockIdx.y;
    const float scale = 0.17677669529663687f;  // 1/sqrt(32)

    if (tid < 29) s_bias[tid] = bt[(tid + 15) * 12 + h];

    // stage q/k/v hi/lo via cp.async (row = tid>>1, two 16B granules)
    {
        const int row = tid >> 1;
        const int cg0 = (tid & 1) * 2;
        const uint32_t d0 = sw64(row, cg0), d1 = sw64(row, cg0 + 1);
        size_t base = ((size_t)win * D + row) * NQKV + (size_t)h * 32 + cg0 * 8;
        const __nv_bfloat16* ph = g_qkv_hi + base;
        const __nv_bfloat16* pl = g_qkv_lo + base;
        cp16(sb + AQH + d0, ph);        cp16(sb + AQH + d1, ph + 8);
        cp16(sb + AQL + d0, pl);        cp16(sb + AQL + d1, pl + 8);
        cp16(sb + AKH + d0, ph + 384);  cp16(sb + AKH + d1, ph + 392);
        cp16(sb + AKL + d0, pl + 384);  cp16(sb + AKL + d1, pl + 392);
        cp16(sb + AVH + d0, ph + 768);  cp16(sb + AVH + d1, ph + 776);
        cp16(sb + AVL + d0, pl + 768);  cp16(sb + AVL + d1, pl + 776);
        CP_COMMIT();
    }
    CP_WAIT0();
    __syncthreads();

    const int aro = (lane & 7) + ((lane >> 3) & 1) * 8;
    const int cgs = lane >> 4;

    // Q a-frags (hi/lo), k = e in two 16-steps
    uint32_t qh[2][4], ql[2][4];
#pragma unroll
    for (int ks = 0; ks < 2; ++ks) {
        uint32_t ad = sb + sw64(w * 16 + aro, ks * 2 + cgs);
        ldsm4(qh[ks], ad + AQH);
        ldsm4(ql[ks], ad + AQL);
    }

    // S = Q K^T  (8 n-tiles of 8 cols)
    float sacc[8][4];
#pragma unroll
    for (int nt = 0; nt < 8; ++nt)
#pragma unroll
        for (int q = 0; q < 4; ++q) sacc[nt][q] = 0.f;

#pragma unroll
    for (int jb = 0; jb < 4; ++jb) {
#pragma unroll
        for (int ks = 0; ks < 2; ++ks) {
            uint32_t bd = sb + sw64(jb * 16 + aro, ks * 2 + cgs);
            uint32_t tH[4], tL[4];
            ldsm4(tH, bd + AKH);
            ldsm4(tL, bd + AKL);
            uint32_t bh0[2] = {tH[0], tH[2]}, bh1[2] = {tH[1], tH[3]};
            uint32_t bl0[2] = {tL[0], tL[2]}, bl1[2] = {tL[1], tL[3]};
            mma16816(sacc[jb*2],   qh[ks], bh0);
            mma16816(sacc[jb*2],   qh[ks], bl0);
            mma16816(sacc[jb*2],   ql[ks], bh0);
            mma16816(sacc[jb*2+1], qh[ks], bh1);
            mma16816(sacc[jb*2+1], qh[ks], bl1);
            mma16816(sacc[jb*2+1], ql[ks], bh1);
        }
    }

    // bias + mask + softmax (rows i0, i1 = i0+8)
    const int i0 = w * 16 + (lane >> 2);
    const int i1 = i0 + 8;
    const int jc = 2 * (lane & 3);
    const int wr8 = ((win & 63) >> 3) * 8, wc8 = (win & 7) * 8;
#define SUMOF(t)  (((t) >> 3) + ((t) & 7))
#define REGOF(t)  ({ int _gr = wr8 + ((t) >> 3), _gc = wc8 + ((t) & 7); \
                     (_gr < 56 ? 0 : (_gr < 60 ? 1 : 2)) * 3 + \
                     (_gc < 56 ? 0 : (_gc < 60 ? 1 : 2)); })
    const int isum0 = SUMOF(i0), ireg0 = REGOF(i0);
    const int isum1 = SUMOF(i1), ireg1 = REGOF(i1);

    float mx0 = -1e30f, mx1 = -1e30f;
#pragma unroll
    for (int nt = 0; nt < 8; ++nt) {
        int j0 = nt * 8 + jc, j1 = j0 + 1;
        int jsum0 = SUMOF(j0), jreg0 = REGOF(j0);
        int jsum1 = jsum0 + 1,  jreg1 = REGOF(j1);
        float s0 = sacc[nt][0] * scale + s_bias[isum0 - jsum0 + 14] + (ireg0 == jreg0 ? 0.f : -100.f);
        float s1 = sacc[nt][1] * scale + s_bias[isum0 - jsum1 + 14] + (ireg0 == jreg1 ? 0.f : -100.f);
        float s2 = sacc[nt][2] * scale + s_bias[isum1 - jsum0 + 14] + (ireg1 == jreg0 ? 0.f : -100.f);
        float s3 = sacc[nt][3] * scale + s_bias[isum1 - jsum1 + 14] + (ireg1 == jreg1 ? 0.f : -100.f);
        sacc[nt][0] = s0; sacc[nt][1] = s1; sacc[nt][2] = s2; sacc[nt][3] = s3;
        mx0 = fmaxf(mx0, fmaxf(s0, s1));
        mx1 = fmaxf(mx1, fmaxf(s2, s3));
    }
    mx0 = fmaxf(mx0, __shfl_xor_sync(0xffffffffu, mx0, 1));
    mx0 = fmaxf(mx0, __shfl_xor_sync(0xffffffffu, mx0, 2));
    mx1 = fmaxf(mx1, __shfl_xor_sync(0xffffffffu, mx1, 1));
    mx1 = fmaxf(mx1, __shfl_xor_sync(0xffffffffu, mx1, 2));

    float sum0 = 0.f, sum1 = 0.f;
#pragma unroll
    for (int nt = 0; nt < 8; ++nt) {
        float e0 = __expf(sacc[nt][0] - mx0);
        float e1 = __expf(sacc[nt][1] - mx0);
        float e2 = __expf(sacc[nt][2] - mx1);
        float e3 = __expf(sacc[nt][3] - mx1);
        sacc[nt][0] = e0; sacc[nt][1] = e1; sacc[nt][2] = e2; sacc[nt][3] = e3;
        sum0 += e0 + e1; sum1 += e2 + e3;
    }
    sum0 += __shfl_xor_sync(0xffffffffu, sum0, 1);
    sum0 += __shfl_xor_sync(0xffffffffu, sum0, 2);
    sum1 += __shfl_xor_sync(0xffffffffu, sum1, 1);
    sum1 += __shfl_xor_sync(0xffffffffu, sum1, 2);
    float inv0 = 1.f / sum0, inv1 = 1.f / sum1;
#pragma unroll
    for (int nt = 0; nt < 8; ++nt) {
        sacc[nt][0] *= inv0; sacc[nt][1] *= inv0;
        sacc[nt][2] *= inv1; sacc[nt][3] *= inv1;
    }

    // O = P V   (4 n-tiles over e=32, k = j in 4 16-steps)
    float oacc[4][4];
#pragma unroll
    for (int nt = 0; nt < 4; ++nt)
#pragma unroll
        for (int q = 0; q < 4; ++q) oacc[nt][q] = 0.f;

#pragma unroll
    for (int s = 0; s < 4; ++s) {
        // P frag (A-layout) from sacc tiles 2s, 2s+1: hi & lo splits
        uint32_t ah[4], al[4];
#pragma unroll
        for (int half = 0; half < 2; ++half) {
            float* t = sacc[2*s + half];
            uint16_t h0, l0, h1, l1, h2, l2, h3, l3;
            split_bf16(t[0], h0, l0); split_bf16(t[1], h1, l1);
            split_bf16(t[2], h2, l2); split_bf16(t[3], h3, l3);
            ah[half*2]     = (uint32_t)h0 | ((uint32_t)h1 << 16);
            ah[half*2 + 1] = (uint32_t)h2 | ((uint32_t)h3 << 16);
            al[half*2]     = (uint32_t)l0 | ((uint32_t)l1 << 16);
            al[half*2 + 1] = (uint32_t)l2 | ((uint32_t)l3 << 16);
        }
#pragma unroll
        for (int half = 0; half < 2; ++half) {
            uint32_t bd = sb + sw64(s * 16 + aro, half * 2 + cgs);
            uint32_t tH[4], tL[4];
            ldsm4t(tH, bd + AVH);
            ldsm4t(tL, bd + AVL);
            uint32_t bh0[2] = {tH[0], tH[1]}, bh1[2] = {tH[2], tH[3]};
            uint32_t bl0[2] = {tL[0], tL[1]}, bl1[2] = {tL[2], tL[3]};
            mma16816(oacc[half*2],   ah, bh0);
            mma16816(oacc[half*2],   al, bh0);
            mma16816(oacc[half*2],   ah, bl0);
            mma16816(oacc[half*2+1], ah, bh1);
            mma16816(oacc[half*2+1], al, bh1);
            mma16816(oacc[half*2+1], ah, bl1);
        }
    }

    // write ctx (bf16 hi/lo)
#pragma unroll
    for (int nt = 0; nt < 4; ++nt) {
        int e0 = h * 32 + nt * 8 + jc;
        size_t o0 = ((size_t)win * D + i0) * C + e0;
        size_t o1 = ((size_t)win * D + i1) * C + e0;
        uint16_t h0, l0, h1, l1;
        split_bf16(oacc[nt][0], h0, l0); split_bf16(oacc[nt][1], h1, l1);
        *(uint32_t*)&g_ctx_hi[o0] = (uint32_t)h0 | ((uint32_t)h1 << 16);
        *(uint32_t*)&g_ctx_lo[o0] = (uint32_t)l0 | ((uint32_t)l1 << 16);
        split_bf16(oacc[nt][2], h0, l0); split_bf16(oacc[nt][3], h1, l1);
        *(uint32_t*)&g_ctx_hi[o1] = (uint32_t)h0 | ((uint32_t)h1 << 16);
        *(uint32_t*)&g_ctx_lo[o1] = (uint32_t)l0 | ((uint32_t)l1 << 16);
    }
}

// ---------------------------------------------------------------------------
// Kernel 3: projection + window-reverse/roll scatter. grid = (3, 1024).
// ---------------------------------------------------------------------------
__global__ __launch_bounds__(256) void proj_mma(
    const float* __restrict__ bias, float* __restrict__ out)
{
    extern __shared__ char smem[];
    const uint32_t sb = smem_u32(smem);
    const int tid = threadIdx.x, lane = tid & 31, wid = tid >> 5;
    const int wpair = blockIdx.y;
    const int n0 = blockIdx.x * 128;
    const int wm = (wid & 1) * 64, wn = (wid >> 1) * 32;

    const int row = tid >> 1;
    const int cg0 = (tid & 1) * 2;
    const uint32_t d0 = sw64(row, cg0), d1 = sw64(row, cg0 + 1);
    size_t tok = (size_t)wpair * 128 + row;
    const __nv_bfloat16* pAh = g_ctx_hi + tok * C + cg0 * 8;
    const __nv_bfloat16* pAl = g_ctx_lo + tok * C + cg0 * 8;
    const __nv_bfloat16* pBh = g_wout_hi + (size_t)(n0 + row) * C + cg0 * 8;
    const __nv_bfloat16* pBl = g_wout_lo + (size_t)(n0 + row) * C + cg0 * 8;

    float acc[4][4][4];
#pragma unroll
    for (int mi = 0; mi < 4; ++mi)
#pragma unroll
        for (int ni = 0; ni < 4; ++ni)
#pragma unroll
            for (int q = 0; q < 4; ++q) acc[mi][ni][q] = 0.f;

    {
        uint32_t s0 = sb;
        cp16(s0 + SA_HI + d0, pAh); cp16(s0 + SA_HI + d1, pAh + 8);
        cp16(s0 + SA_LO + d0, pAl); cp16(s0 + SA_LO + d1, pAl + 8);
        cp16(s0 + SB_HI + d0, pBh); cp16(s0 + SB_HI + d1, pBh + 8);
        cp16(s0 + SB_LO + d0, pBl); cp16(s0 + SB_LO + d1, pBl + 8);
        CP_COMMIT();
    }
    for (int it = 0; it < NCHUNK; ++it) {
        if (it + 1 < NCHUNK) {
            int k0 = (it + 1) * KCH;
            uint32_t s0 = sb + ((it + 1) & 1) * STAGE_STRIDE;
            cp16(s0 + SA_HI + d0, pAh + k0); cp16(s0 + SA_HI + d1, pAh + k0 + 8);
            cp16(s0 + SA_LO + d0, pAl + k0); cp16(s0 + SA_LO + d1, pAl + k0 + 8);
            cp16(s0 + SB_HI + d0, pBh + k0); cp16(s0 + SB_HI + d1, pBh + k0 + 8);
            cp16(s0 + SB_LO + d0, pBl + k0); cp16(s0 + SB_LO + d1, pBl + k0 + 8);
            CP_COMMIT();
            CP_WAIT1();
        } else {
            CP_WAIT0();
        }
        __syncthreads();
        mma_stage(sb + (it & 1) * STAGE_STRIDE, lane, wm, wn, acc);
        __syncthreads();
    }

    float (*S)[132] = (float(*)[132])smem;
    acc_to_smem(S, tid, acc);
    __syncthreads();

    const float4 bb = *(const float4*)&bias[n0 + lane * 4];
#pragma unroll
    for (int p = 0; p < 16; ++p) {
        int r = p * 8 + wid;
        float4 v = *(const float4*)&S[r][lane * 4];
        v.x += bb.x; v.y += bb.y; v.z += bb.z; v.w += bb.w;
        int tk = wpair * 128 + r;
        int win = tk >> 6;
        int img = win >> 6, wi = win & 63, wr = wi >> 3, wc = wi & 7;
        int t = tk & 63, ri = t >> 3, ci = t & 7;
        int gr = (wr * 8 + ri + 4) & 63;   // window-reverse + roll(+4) == +4 mod 64
        int gc = (wc * 8 + ci + 4) & 63;
        *(float4*)(out + (((size_t)img * 64 + gr) * 64 + gc) * C + n0 + lane * 4) = v;
    }
}

// ---------------------------------------------------------------------------
namespace {
struct ForceLoad {
    ForceLoad() {
        void* p = nullptr;
        cudaGetSymbolAddress(&p, g_qkv_hi);
        cudaGetSymbolAddress(&p, g_ctx_hi);
        cudaFuncSetAttribute(qkv_mma,  cudaFuncAttributeMaxDynamicSharedMemorySize, SMEM_BYTES);
        cudaFuncSetAttribute(proj_mma, cudaFuncAttributeMaxDynamicSharedMemorySize, SMEM_BYTES);
    }
};
ForceLoad g_force_load;
}

extern "C" void kernel_launch(void* const* d_in, const int* in_sizes, int n_in,
                              void* d_out, int out_size)
{
    (void)in_sizes; (void)n_in; (void)out_size;
    const float* x      = (const float*)d_in[0];
    const float* w_qkv  = (const float*)d_in[1];
    const float* b_qkv  = (const float*)d_in[2];
    const float* w_out  = (const float*)d_in[3];
    const float* b_out  = (const float*)d_in[4];
    const float* btab   = (const float*)d_in[5];
    float* out = (float*)d_out;

    prep_x   <<<49152, 256>>>(x);
    prep_wqkv<<<432, 256>>>(w_qkv);
    prep_wout<<<144, 256>>>(w_out);
    qkv_mma  <<<dim3(9, NWIN / 2), 256, SMEM_BYTES>>>(b_qkv);
    attn_mma <<<dim3(NWIN, 12), 128>>>(btab);
    proj_mma <<<dim3(3, NWIN / 2), 256, SMEM_BYTES>>>(b_out, out);
}